// round 1
// baseline (speedup 1.0000x reference)
#include <cuda_runtime.h>
#include <math.h>

// SimpleLSTM: B=64, S=1024, I=256, H=512, O=256
// Inputs (metadata order):
//  0: x     [64,1024,256] f32
//  1: W_f   [768,512] f32   rows 0..255 = x part, 256..767 = h part
//  2: b_f   [512]
//  3: W_i   [768,512]
//  4: b_i   [512]
//  5: W_c   [768,512]
//  6: b_c   [512]
//  7: W_o   [768,512]
//  8: b_o   [512]
//  9: W_out [512,256]
// 10: b_out [256]
// out: [64,256] f32

#define BB 64
#define SS 1024
#define II 256
#define HH 512
#define OO 256
#define G4 2048          // 4*H gate columns

#define NCTA 128         // persistent step-kernel CTAs (one wave)
#define CPC  16          // gate cols per CTA
#define HPC  4           // h cols per CTA

// -------- device scratch (static __device__ arrays: allowed, no allocs) ----
__device__ float    g_gx[(size_t)SS * BB * G4];   // [s][b][col]  (512 MB)
__device__ float    g_hbuf[2][HH * BB];           // h double buffer, [k][b]
__device__ unsigned g_bar_gen;
__device__ unsigned g_bar_cnt;

// ---------------------------------------------------------------- init ----
__global__ void init_kernel() {
    int t = blockIdx.x * blockDim.x + threadIdx.x;
    int n = 2 * HH * BB;
    for (int i = t; i < n; i += gridDim.x * blockDim.x)
        ((float*)g_hbuf)[i] = 0.0f;
    if (t == 0) { g_bar_gen = 0u; g_bar_cnt = 0u; }
}

// ---------------------------------------------- input projection GEMM -----
// Gx[s][b][col] = sum_{i<256} x[b][s][i] * W_g[i][j] + b_g[j]
// Tile: 64 s-rows x 64 cols per block, K=256, one b per blockIdx.z.
__global__ void __launch_bounds__(256) precompute_kernel(
    const float* __restrict__ x,
    const float* __restrict__ Wf, const float* __restrict__ Wi,
    const float* __restrict__ Wc, const float* __restrict__ Wo,
    const float* __restrict__ bf, const float* __restrict__ bi,
    const float* __restrict__ bc, const float* __restrict__ bo)
{
    __shared__ float As[16][64];   // [k][s]
    __shared__ float Bs[16][64];   // [k][n]

    const int b  = blockIdx.z;
    const int s0 = blockIdx.y * 64;
    const int c0 = blockIdx.x * 64;          // global gate col tile base
    const int g  = c0 >> 9;                  // gate id (tile never crosses 512)
    const int j0 = c0 & 511;                 // col within gate

    const float* W    = (g == 0) ? Wf : (g == 1) ? Wi : (g == 2) ? Wc : Wo;
    const float* bias = (g == 0) ? bf : (g == 1) ? bi : (g == 2) ? bc : bo;

    const int t  = threadIdx.x;
    const int tx = t & 15;
    const int ty = t >> 4;

    float acc[4][4] = {};

    const int sr = t >> 2;          // s row this thread loads (0..63)
    const int kq = (t & 3) * 4;     // k quad

    for (int k0 = 0; k0 < II; k0 += 16) {
        // A: x[b][s0+sr][k0+kq .. +3]  -> As[k][s]
        float4 av = *(const float4*)&x[((size_t)b * SS + s0 + sr) * II + k0 + kq];
        As[kq + 0][sr] = av.x; As[kq + 1][sr] = av.y;
        As[kq + 2][sr] = av.z; As[kq + 3][sr] = av.w;
        // B: W[(k0+kk)][j0+nn] -> Bs[kk][nn]   (coalesced over nn)
        #pragma unroll
        for (int i = 0; i < 4; i++) {
            int e  = t + i * 256;
            int kk = e >> 6, nn = e & 63;
            Bs[kk][nn] = W[(size_t)(k0 + kk) * HH + j0 + nn];
        }
        __syncthreads();
        #pragma unroll
        for (int k = 0; k < 16; k++) {
            float a0 = As[k][ty * 4 + 0], a1 = As[k][ty * 4 + 1];
            float a2 = As[k][ty * 4 + 2], a3 = As[k][ty * 4 + 3];
            float w0 = Bs[k][tx * 4 + 0], w1 = Bs[k][tx * 4 + 1];
            float w2 = Bs[k][tx * 4 + 2], w3 = Bs[k][tx * 4 + 3];
            acc[0][0] += a0 * w0; acc[0][1] += a0 * w1; acc[0][2] += a0 * w2; acc[0][3] += a0 * w3;
            acc[1][0] += a1 * w0; acc[1][1] += a1 * w1; acc[1][2] += a1 * w2; acc[1][3] += a1 * w3;
            acc[2][0] += a2 * w0; acc[2][1] += a2 * w1; acc[2][2] += a2 * w2; acc[2][3] += a2 * w3;
            acc[3][0] += a3 * w0; acc[3][1] += a3 * w1; acc[3][2] += a3 * w2; acc[3][3] += a3 * w3;
        }
        __syncthreads();
    }

    #pragma unroll
    for (int mi = 0; mi < 4; mi++) {
        int s = s0 + ty * 4 + mi;
        float4 v;
        v.x = acc[mi][0] + bias[j0 + tx * 4 + 0];
        v.y = acc[mi][1] + bias[j0 + tx * 4 + 1];
        v.z = acc[mi][2] + bias[j0 + tx * 4 + 2];
        v.w = acc[mi][3] + bias[j0 + tx * 4 + 3];
        *(float4*)&g_gx[((size_t)s * BB + b) * G4 + c0 + tx * 4] = v;
    }
}

// ----------------------------------------- persistent recurrent kernel ----
// CTA `cta` owns h-cols j = cta*4 .. cta*4+3 and their 4 gate columns.
// smem: h_s[512][64] (128KB) | W_s[512][16] (32KB) | gbuf[16][64] (4KB)
#define SMEM_FLOATS (HH * BB + HH * CPC + CPC * BB)

__global__ void __launch_bounds__(256, 1) step_kernel(
    const float* __restrict__ Wf, const float* __restrict__ Wi,
    const float* __restrict__ Wc, const float* __restrict__ Wo)
{
    extern __shared__ float sm[];
    float* h_s  = sm;                       // [k][b]
    float* W_s  = sm + HH * BB;             // [k][cc]  cc = gate*4 + l
    float* gbuf = sm + HH * BB + HH * CPC;  // [cc][b]

    const int cta = blockIdx.x;
    const int t   = threadIdx.x;

    // Load this CTA's W_h slice once (rows 256..767 of each gate matrix).
    for (int e = t; e < HH * CPC; e += 256) {
        int k = e >> 4, cc = e & 15;
        int g = cc >> 2, l = cc & 3;
        const float* W = (g == 0) ? Wf : (g == 1) ? Wi : (g == 2) ? Wc : Wo;
        W_s[k * CPC + cc] = W[(size_t)(II + k) * HH + cta * HPC + l];
    }

    // GEMM thread tile: 2 batches x 2 gate cols.
    const int tb = t & 31, tc = t >> 5;
    const int b0 = tb * 2;
    const int c0 = tc * 2;                               // local cc base (even)
    const int colg = (c0 >> 2) * HH + cta * HPC + (c0 & 3); // global gate col

    // Update-phase thread: one (batch, local h-col) cell; c lives in a reg.
    const int ub = t & 63, ul = t >> 6;
    float c_reg = 0.0f;

    for (int s = 0; s < SS; s++) {
        const int par = s & 1;

        // Stage h (L2 -> smem), bypass L1 (other SMs wrote it).
        {
            const float4* hsrc = (const float4*)g_hbuf[par];
            float4*       hdst = (float4*)h_s;
            #pragma unroll
            for (int e = t; e < (HH * BB) / 4; e += 256)
                hdst[e] = __ldcg(hsrc + e);
        }
        // Accumulators start from the precomputed x-projection (+bias).
        const float* gx = &g_gx[(size_t)s * BB * G4];
        float acc00 = gx[(size_t)(b0    ) * G4 + colg    ];
        float acc01 = gx[(size_t)(b0    ) * G4 + colg + 1];
        float acc10 = gx[(size_t)(b0 + 1) * G4 + colg    ];
        float acc11 = gx[(size_t)(b0 + 1) * G4 + colg + 1];
        __syncthreads();

        #pragma unroll 8
        for (int k = 0; k < HH; k++) {
            float2 hv = *(const float2*)&h_s[k * BB + b0];
            float2 wv = *(const float2*)&W_s[k * CPC + c0];
            acc00 += hv.x * wv.x; acc01 += hv.x * wv.y;
            acc10 += hv.y * wv.x; acc11 += hv.y * wv.y;
        }

        gbuf[(c0    ) * BB + b0    ] = acc00;
        gbuf[(c0 + 1) * BB + b0    ] = acc01;
        gbuf[(c0    ) * BB + b0 + 1] = acc10;
        gbuf[(c0 + 1) * BB + b0 + 1] = acc11;
        __syncthreads();

        // Gates + cell update for this thread's (b, l).
        {
            float gf = gbuf[(0 * HPC + ul) * BB + ub];
            float gi = gbuf[(1 * HPC + ul) * BB + ub];
            float gu = gbuf[(2 * HPC + ul) * BB + ub];
            float go = gbuf[(3 * HPC + ul) * BB + ub];
            float f = 1.0f / (1.0f + expf(-gf));
            float i = 1.0f / (1.0f + expf(-gi));
            float u = tanhf(gu);
            float o = 1.0f / (1.0f + expf(-go));
            c_reg = f * c_reg + i * u;
            float hnew = o * tanhf(c_reg);
            g_hbuf[1 - par][(cta * HPC + ul) * BB + ub] = hnew;
        }

        // Make h writes visible, then chip-wide sense barrier.
        __threadfence();
        __syncthreads();
        if (t == 0) {
            unsigned arrived = atomicAdd(&g_bar_cnt, 1u);
            if (arrived == NCTA - 1) {
                atomicExch(&g_bar_cnt, 0u);
                __threadfence();
                atomicAdd(&g_bar_gen, 1u);
            } else {
                while (atomicAdd(&g_bar_gen, 0u) < (unsigned)(s + 1)) { }
            }
        }
        __syncthreads();
    }
}

// -------------------------------------------------------- output head -----
__global__ void __launch_bounds__(256) out_kernel(
    const float* __restrict__ Wout, const float* __restrict__ bout,
    float* __restrict__ out)
{
    __shared__ float hsh[HH];
    const int b = blockIdx.x;
    const int j = threadIdx.x;
    for (int k = j; k < HH; k += 256)
        hsh[k] = g_hbuf[0][k * BB + b];   // final h lives in buffer 0
    __syncthreads();

    float a0 = 0.f, a1 = 0.f, a2 = 0.f, a3 = 0.f;
    #pragma unroll 4
    for (int k = 0; k < HH; k += 4) {
        a0 += hsh[k + 0] * Wout[(size_t)(k + 0) * OO + j];
        a1 += hsh[k + 1] * Wout[(size_t)(k + 1) * OO + j];
        a2 += hsh[k + 2] * Wout[(size_t)(k + 2) * OO + j];
        a3 += hsh[k + 3] * Wout[(size_t)(k + 3) * OO + j];
    }
    out[(size_t)b * OO + j] = a0 + a1 + a2 + a3 + bout[j];
}

// ------------------------------------------------------------ launcher ----
extern "C" void kernel_launch(void* const* d_in, const int* in_sizes, int n_in,
                              void* d_out, int out_size)
{
    (void)in_sizes; (void)n_in; (void)out_size;
    const float* x    = (const float*)d_in[0];
    const float* Wf   = (const float*)d_in[1];
    const float* bf   = (const float*)d_in[2];
    const float* Wi   = (const float*)d_in[3];
    const float* bi   = (const float*)d_in[4];
    const float* Wc   = (const float*)d_in[5];
    const float* bc   = (const float*)d_in[6];
    const float* Wo   = (const float*)d_in[7];
    const float* bo   = (const float*)d_in[8];
    const float* Wout = (const float*)d_in[9];
    const float* bout = (const float*)d_in[10];
    float* out = (float*)d_out;

    cudaFuncSetAttribute(step_kernel,
                         cudaFuncAttributeMaxDynamicSharedMemorySize,
                         SMEM_FLOATS * (int)sizeof(float));

    init_kernel<<<32, 256>>>();
    precompute_kernel<<<dim3(G4 / 64, SS / 64, BB), 256>>>(
        x, Wf, Wi, Wc, Wo, bf, bi, bc, bo);
    step_kernel<<<NCTA, 256, SMEM_FLOATS * (int)sizeof(float)>>>(Wf, Wi, Wc, Wo);
    out_kernel<<<BB, 256>>>(Wout, bout, out);
}

// round 3
// speedup vs baseline: 1.1801x; 1.1801x over previous
#include <cuda_runtime.h>
#include <math.h>

// SimpleLSTM: B=64, S=1024, I=256, H=512, O=256
// W_* are [768,512]: rows 0..255 x-part, 256..767 h-part (verified R1, rel_err 6e-7).

#define BB 64
#define SS 1024
#define II 256
#define HH 512
#define OO 256
#define G4 2048

#define NCTA 128
#define CPC  16          // gate cols per CTA
#define HPC  4           // h cols per CTA
#define GPITCH 17        // conflict-free gate-buffer pitch

// ---------------------------------------------------------------- f32x2 ----
__device__ __forceinline__ unsigned long long pack2(float lo, float hi) {
    unsigned long long r;
    asm("mov.b64 %0, {%1, %2};" : "=l"(r) : "f"(lo), "f"(hi));
    return r;
}
__device__ __forceinline__ unsigned long long ffma2(
    unsigned long long a, unsigned long long b, unsigned long long c) {
    unsigned long long d;
    asm("fma.rn.f32x2 %0, %1, %2, %3;" : "=l"(d) : "l"(a), "l"(b), "l"(c));
    return d;
}
__device__ __forceinline__ float2 unpack2(unsigned long long v) {
    float2 f;
    asm("mov.b64 {%0, %1}, %2;" : "=f"(f.x), "=f"(f.y) : "l"(v));
    return f;
}

// -------- device scratch ----------------------------------------------------
__device__ float    g_gx[(size_t)SS * BB * G4];   // [s][b][col]
__device__ float    g_hbuf[2][HH * BB];           // [k][b]
__device__ unsigned g_bar_gen;
__device__ unsigned g_bar_cnt;

// ---------------------------------------------------------------- init ----
__global__ void init_kernel() {
    int t = blockIdx.x * blockDim.x + threadIdx.x;
    int n = 2 * HH * BB;
    for (int i = t; i < n; i += gridDim.x * blockDim.x)
        ((float*)g_hbuf)[i] = 0.0f;
    if (t == 0) { g_bar_gen = 0u; g_bar_cnt = 0u; }
}

// ---------------------------------------------- input projection GEMM -----
// Gx[s][b][col] = x[b][s][:] @ W_g[0:256][:] + b_g ;  64x64 tile, f32x2 inner.
__global__ void __launch_bounds__(256) precompute_kernel(
    const float* __restrict__ x,
    const float* __restrict__ Wf, const float* __restrict__ Wi,
    const float* __restrict__ Wc, const float* __restrict__ Wo,
    const float* __restrict__ bf, const float* __restrict__ bi,
    const float* __restrict__ bc, const float* __restrict__ bo)
{
    __shared__ float As[16][64];   // [k][s]
    __shared__ float Bs[16][64];   // [k][n]

    const int b  = blockIdx.z;
    const int s0 = blockIdx.y * 64;
    const int c0 = blockIdx.x * 64;
    const int g  = c0 >> 9;
    const int j0 = c0 & 511;

    const float* W    = (g == 0) ? Wf : (g == 1) ? Wi : (g == 2) ? Wc : Wo;
    const float* bias = (g == 0) ? bf : (g == 1) ? bi : (g == 2) ? bc : bo;

    const int t  = threadIdx.x;
    const int tx = t & 15;
    const int ty = t >> 4;

    unsigned long long acc[4][2] = {};

    const int sr = t >> 2;
    const int kq = (t & 3) * 4;

    for (int k0 = 0; k0 < II; k0 += 16) {
        float4 av = *(const float4*)&x[((size_t)b * SS + s0 + sr) * II + k0 + kq];
        As[kq + 0][sr] = av.x; As[kq + 1][sr] = av.y;
        As[kq + 2][sr] = av.z; As[kq + 3][sr] = av.w;
        #pragma unroll
        for (int i = 0; i < 4; i++) {
            int e  = t + i * 256;
            int kk = e >> 6, nn = e & 63;
            Bs[kk][nn] = W[(size_t)(k0 + kk) * HH + j0 + nn];
        }
        __syncthreads();
        #pragma unroll
        for (int k = 0; k < 16; k++) {
            float4 a = *(const float4*)&As[k][ty * 4];
            ulonglong2 w = *(const ulonglong2*)&Bs[k][tx * 4];
            unsigned long long aa;
            aa = pack2(a.x, a.x);
            acc[0][0] = ffma2(aa, w.x, acc[0][0]); acc[0][1] = ffma2(aa, w.y, acc[0][1]);
            aa = pack2(a.y, a.y);
            acc[1][0] = ffma2(aa, w.x, acc[1][0]); acc[1][1] = ffma2(aa, w.y, acc[1][1]);
            aa = pack2(a.z, a.z);
            acc[2][0] = ffma2(aa, w.x, acc[2][0]); acc[2][1] = ffma2(aa, w.y, acc[2][1]);
            aa = pack2(a.w, a.w);
            acc[3][0] = ffma2(aa, w.x, acc[3][0]); acc[3][1] = ffma2(aa, w.y, acc[3][1]);
        }
        __syncthreads();
    }

    float4 bv = *(const float4*)&bias[j0 + tx * 4];
    #pragma unroll
    for (int mi = 0; mi < 4; mi++) {
        int s = s0 + ty * 4 + mi;
        float2 q0 = unpack2(acc[mi][0]);
        float2 q1 = unpack2(acc[mi][1]);
        float4 v;
        v.x = q0.x + bv.x; v.y = q0.y + bv.y;
        v.z = q1.x + bv.z; v.w = q1.y + bv.w;
        *(float4*)&g_gx[((size_t)s * BB + b) * G4 + c0 + tx * 4] = v;
    }
}

// ----------------------------------------- persistent recurrent kernel ----
// CTA owns gate cols {g*512 + cta*4 + l : g<4, l<4}. 256 threads:
//  GEMM phase: 2 k-split groups of 128; thread tile = 1 batch x 8 gate cols.
//  Update phase: thread t owns cell (b=t&63, l=t>>6); c in a register.
#define SMEM_FLOATS (HH * BB + HH * CPC + 2 * BB * GPITCH)

__global__ void __launch_bounds__(256, 1) step_kernel(
    const float* __restrict__ Wf, const float* __restrict__ Wi,
    const float* __restrict__ Wc, const float* __restrict__ Wo)
{
    extern __shared__ float sm[];
    float* h_s  = sm;                        // [k][b]   512x64
    float* W_s  = sm + HH * BB;              // [k][cc]  512x16
    float* gbuf = sm + HH * BB + HH * CPC;   // 2 slabs of [b][GPITCH]

    const int cta = blockIdx.x;
    const int t   = threadIdx.x;

    // Load W_h slice (rows 256..767), once.
    for (int e = t; e < HH * CPC; e += 256) {
        int k = e >> 4, cc = e & 15;
        int g = cc >> 2, l = cc & 3;
        const float* W = (g == 0) ? Wf : (g == 1) ? Wi : (g == 2) ? Wc : Wo;
        W_s[k * CPC + cc] = W[(size_t)(II + k) * HH + cta * HPC + l];
    }

    const int kg = t >> 7;           // k-split group 0/1
    const int t2 = t & 127;
    const int ty = t2 >> 6;          // col half: cc base = ty*8
    const int b  = t2 & 63;
    const int c0 = ty * 8;
    const int k0 = kg * (HH / 2);
    float* gslab = gbuf + kg * (BB * GPITCH);

    const int ub = t & 63, ul = t >> 6;   // update-phase cell (b, l)
    float c_reg = 0.0f;

    for (int s = 0; s < SS; s++) {
        const int par = s & 1;

        // Stage h: L2 -> smem (bypass L1; other SMs wrote it).
        {
            const float4* hsrc = (const float4*)g_hbuf[par];
            float4*       hdst = (float4*)h_s;
            #pragma unroll
            for (int e = t; e < (HH * BB) / 4; e += 256)
                hdst[e] = __ldcg(hsrc + e);
        }

        // Accumulators: group 0 seeds from precomputed Gx (+bias), group 1 zero.
        unsigned long long a0, a1, a2, a3;
        if (kg == 0) {
            const float* gx = &g_gx[(size_t)s * BB * G4 + (size_t)b * G4 + cta * HPC];
            float4 ga = *(const float4*)&gx[(ty * 2    ) * HH];
            float4 gb = *(const float4*)&gx[(ty * 2 + 1) * HH];
            a0 = pack2(ga.x, ga.y); a1 = pack2(ga.z, ga.w);
            a2 = pack2(gb.x, gb.y); a3 = pack2(gb.z, gb.w);
        } else {
            a0 = a1 = a2 = a3 = 0ull;
        }
        __syncthreads();

        #pragma unroll 8
        for (int k = k0; k < k0 + HH / 2; k++) {
            float h = h_s[k * BB + b];
            unsigned long long hh = pack2(h, h);
            ulonglong2 wA = *(const ulonglong2*)&W_s[k * CPC + c0];
            ulonglong2 wB = *(const ulonglong2*)&W_s[k * CPC + c0 + 4];
            a0 = ffma2(hh, wA.x, a0); a1 = ffma2(hh, wA.y, a1);
            a2 = ffma2(hh, wB.x, a2); a3 = ffma2(hh, wB.y, a3);
        }

        // Spill partials to the (bank-conflict-free) gate buffer.
        {
            float2 p;
            float* row = &gslab[b * GPITCH + c0];
            p = unpack2(a0); row[0] = p.x; row[1] = p.y;
            p = unpack2(a1); row[2] = p.x; row[3] = p.y;
            p = unpack2(a2); row[4] = p.x; row[5] = p.y;
            p = unpack2(a3); row[6] = p.x; row[7] = p.y;
        }
        __syncthreads();

        // Gates + cell update: sum the two k-partials.
        {
            const float* r0 = &gbuf[ub * GPITCH];
            const float* r1 = &gbuf[BB * GPITCH + ub * GPITCH];
            float gf = r0[0 * HPC + ul] + r1[0 * HPC + ul];
            float gi = r0[1 * HPC + ul] + r1[1 * HPC + ul];
            float gu = r0[2 * HPC + ul] + r1[2 * HPC + ul];
            float go = r0[3 * HPC + ul] + r1[3 * HPC + ul];
            float f = 1.0f / (1.0f + expf(-gf));
            float i = 1.0f / (1.0f + expf(-gi));
            float u = tanhf(gu);
            float o = 1.0f / (1.0f + expf(-go));
            c_reg = f * c_reg + i * u;
            float hnew = o * tanhf(c_reg);
            g_hbuf[1 - par][(cta * HPC + ul) * BB + ub] = hnew;
        }

        // Publish h, then chip-wide monotonic barrier with acquire on exit.
        __threadfence();
        __syncthreads();
        if (t == 0) {
            unsigned arrived = atomicAdd(&g_bar_cnt, 1u) + 1u;
            if (arrived == (unsigned)NCTA * (unsigned)(s + 1)) {
                __threadfence();
                atomicAdd(&g_bar_gen, 1u);          // release
            } else {
                unsigned gen;
                do {
                    asm volatile("ld.acquire.gpu.u32 %0, [%1];"
                                 : "=r"(gen) : "l"(&g_bar_gen) : "memory");
                } while (gen <= (unsigned)s);
            }
            __threadfence();   // acquire fence: order flag -> subsequent h reads
        }
        __syncthreads();
    }
}

// -------------------------------------------------------- output head -----
__global__ void __launch_bounds__(256) out_kernel(
    const float* __restrict__ Wout, const float* __restrict__ bout,
    float* __restrict__ out)
{
    __shared__ float hsh[HH];
    const int b = blockIdx.x;
    const int j = threadIdx.x;
    for (int k = j; k < HH; k += 256)
        hsh[k] = g_hbuf[0][k * BB + b];
    __syncthreads();

    float a0 = 0.f, a1 = 0.f, a2 = 0.f, a3 = 0.f;
    #pragma unroll 4
    for (int k = 0; k < HH; k += 4) {
        a0 += hsh[k + 0] * Wout[(size_t)(k + 0) * OO + j];
        a1 += hsh[k + 1] * Wout[(size_t)(k + 1) * OO + j];
        a2 += hsh[k + 2] * Wout[(size_t)(k + 2) * OO + j];
        a3 += hsh[k + 3] * Wout[(size_t)(k + 3) * OO + j];
    }
    out[(size_t)b * OO + j] = a0 + a1 + a2 + a3 + bout[j];
}

// ------------------------------------------------------------ launcher ----
extern "C" void kernel_launch(void* const* d_in, const int* in_sizes, int n_in,
                              void* d_out, int out_size)
{
    (void)in_sizes; (void)n_in; (void)out_size;
    const float* x    = (const float*)d_in[0];
    const float* Wf   = (const float*)d_in[1];
    const float* bf   = (const float*)d_in[2];
    const float* Wi   = (const float*)d_in[3];
    const float* bi   = (const float*)d_in[4];
    const float* Wc   = (const float*)d_in[5];
    const float* bc   = (const float*)d_in[6];
    const float* Wo   = (const float*)d_in[7];
    const float* bo   = (const float*)d_in[8];
    const float* Wout = (const float*)d_in[9];
    const float* bout = (const float*)d_in[10];
    float* out = (float*)d_out;

    cudaFuncSetAttribute(step_kernel,
                         cudaFuncAttributeMaxDynamicSharedMemorySize,
                         SMEM_FLOATS * (int)sizeof(float));

    init_kernel<<<32, 256>>>();
    precompute_kernel<<<dim3(G4 / 64, SS / 64, BB), 256>>>(
        x, Wf, Wi, Wc, Wo, bf, bi, bc, bo);
    step_kernel<<<NCTA, 256, SMEM_FLOATS * (int)sizeof(float)>>>(Wf, Wi, Wc, Wo);
    out_kernel<<<BB, 256>>>(Wout, bout, out);
}